// round 11
// baseline (speedup 1.0000x reference)
#include <cuda_runtime.h>
#include <cuda_fp16.h>
#include <cstdint>
#include <cstddef>

#define Bb   4
#define Ss   2048
#define Hh   512
#define NHh  8
#define HDd  64
#define Mm   (Bb*Ss)

// half scratch buffers
__device__ unsigned short g_Q[(size_t)Bb*NHh*Ss*HDd];  // [b,nh,s,hd], *0.125*log2e
__device__ unsigned short g_K[(size_t)Bb*NHh*Ss*HDd];  // [b,nh,s,hd]
__device__ unsigned short g_V[(size_t)Bb*NHh*Ss*HDd];  // [b,nh,hd,s] TRANSPOSED
__device__ unsigned short g_A[(size_t)Mm*Hh];          // [b,s,h]
// pre-converted half inputs
__device__ unsigned short g_Xq[(size_t)Mm*Hh];
__device__ unsigned short g_Xk[(size_t)Mm*Hh];
__device__ unsigned short g_Xv[(size_t)Mm*Hh];
__device__ unsigned short g_Wh[(size_t)4*Hh*Hh];
// packed mask bits: [b][s][64 words]
__device__ uint32_t g_M[(size_t)Bb*Ss*(Ss/32)];

#define QSCALE 0.1803368801111204f   // 0.125 * log2(e)

__device__ __forceinline__ uint32_t smem_u32(const void* p) {
    uint32_t a;
    asm("{ .reg .u64 t; cvta.to.shared.u64 t, %1; cvt.u32.u64 %0, t; }" : "=r"(a) : "l"(p));
    return a;
}
__device__ __forceinline__ float ex2f(float x) {
    float r; asm("ex2.approx.f32 %0, %1;" : "=f"(r) : "f"(x)); return r;
}
__device__ __forceinline__ uint32_t pack2(float a, float b) {
    __half2 h = __floats2half2_rn(a, b);
    return *(uint32_t*)&h;
}
#define CPASYNC16(dst, src) \
    asm volatile("cp.async.cg.shared.global [%0], [%1], 16;" :: "r"(dst), "l"(src))
#define CPCOMMIT() asm volatile("cp.async.commit_group;" ::: "memory")

#define MMA16(d, a0, a1, a2, a3, b0, b1) \
    asm volatile("mma.sync.aligned.m16n8k16.row.col.f32.f16.f16.f32 " \
        "{%0,%1,%2,%3}, {%4,%5,%6,%7}, {%8,%9}, {%0,%1,%2,%3};" \
        : "+f"((d)[0]), "+f"((d)[1]), "+f"((d)[2]), "+f"((d)[3]) \
        : "r"(a0), "r"(a1), "r"(a2), "r"(a3), "r"(b0), "r"(b1))

#define LDSM4(r, addr) \
    asm volatile("ldmatrix.sync.aligned.m8n8.x4.shared.b16 {%0,%1,%2,%3}, [%4];" \
        : "=r"((r)[0]), "=r"((r)[1]), "=r"((r)[2]), "=r"((r)[3]) : "r"(addr))

// ---------------------------------------------------------------------------
// fused pre-pass: convert q/k/v and 4 weights to half, pack mask bits.
// ---------------------------------------------------------------------------
#define NX4 ((int)((size_t)Mm*Hh/4))        // 1048576
#define NW4 (Hh*Hh/4)                       // 65536
#define NMW ((int)((size_t)Bb*Ss*(Ss/32)))  // 524288
#define CONV_BLOCKS ((3*NX4 + 4*NW4 + NMW)/256)

__global__ __launch_bounds__(256) void conv_all(
    const float* __restrict__ q, const float* __restrict__ k, const float* __restrict__ v,
    const float* __restrict__ Wq, const float* __restrict__ Wk,
    const float* __restrict__ Wv, const float* __restrict__ Wo,
    const int* __restrict__ msk,
    unsigned short* __restrict__ Xq, unsigned short* __restrict__ Xk,
    unsigned short* __restrict__ Xv, unsigned short* __restrict__ Wh,
    uint32_t* __restrict__ Mo)
{
    const int i = blockIdx.x*256 + threadIdx.x;
    if (i < 3*NX4) {
        const int z = i / NX4, idx = i - z*NX4;
        const float* src = (z == 0) ? q : (z == 1) ? k : v;
        unsigned short* dst = (z == 0) ? Xq : (z == 1) ? Xk : Xv;
        float4 f = ((const float4*)src)[idx];
        uint2 o; o.x = pack2(f.x, f.y); o.y = pack2(f.z, f.w);
        ((uint2*)dst)[idx] = o;
    } else if (i < 3*NX4 + 4*NW4) {
        const int j = i - 3*NX4, z = j / NW4, idx = j - z*NW4;
        const float* src = (z == 0) ? Wq : (z == 1) ? Wk : (z == 2) ? Wv : Wo;
        unsigned short* dst = Wh + (size_t)z*Hh*Hh;
        float4 f = ((const float4*)src)[idx];
        uint2 o; o.x = pack2(f.x, f.y); o.y = pack2(f.z, f.w);
        ((uint2*)dst)[idx] = o;
    } else {
        const int w = i - (3*NX4 + 4*NW4);
        const int4* src = (const int4*)(msk + (size_t)w*32);
        uint32_t bits = 0;
        #pragma unroll
        for (int t = 0; t < 8; t++) {
            int4 m = src[t];
            bits |= ((uint32_t)(m.x != 0) << (4*t))   | ((uint32_t)(m.y != 0) << (4*t+1))
                  | ((uint32_t)(m.z != 0) << (4*t+2)) | ((uint32_t)(m.w != 0) << (4*t+3));
        }
        Mo[w] = bits;
    }
}

// ---------------------------------------------------------------------------
// fp16 GEMM core, 3-stage cp.async pipeline.
// out = X[M,512] @ W[512,512]^T + bias. CTA 256 thr, tile 128x64, k-tile 32.
// modes: 0 fp32 [m,n]; 1 Q half head *QSCALE; 2 K half head; 3 V half transposed.
// ---------------------------------------------------------------------------
#define GST2 20    // words per row (16 data + 4 pad)

__device__ __forceinline__ void gemm_core(
    const unsigned short* __restrict__ X, const unsigned short* __restrict__ W,
    const float* __restrict__ bias, void* __restrict__ outv, int mode)
{
    __shared__ uint32_t Xs[3][128*GST2];
    __shared__ uint32_t Ws[3][64*GST2];
    const int tid = threadIdx.x, warp = tid >> 5, lane = tid & 31;
    const int g = lane >> 2, q = lane & 3;
    const int m0 = blockIdx.y << 7, n0b = blockIdx.x << 6;

    const int xr = tid >> 1, xc = (tid & 1) * 2;
    const int wr = tid >> 2, wc = tid & 3;

    const uint32_t xb[3] = { smem_u32(&Xs[0][0]), smem_u32(&Xs[1][0]), smem_u32(&Xs[2][0]) };
    const uint32_t wb[3] = { smem_u32(&Ws[0][0]), smem_u32(&Ws[1][0]), smem_u32(&Ws[2][0]) };
    const uint32_t aoff = (uint32_t)(((warp*16 + ((lane >> 3) & 1)*8 + (lane & 7))*GST2
                          + ((lane >> 4) << 2)) * 4);
    const uint32_t boff = (uint32_t)(((lane & 7)*GST2 + ((lane >> 3) << 2)) * 4);

    float acc[8][4];
    #pragma unroll
    for (int i = 0; i < 8; i++)
        #pragma unroll
        for (int j = 0; j < 4; j++) acc[i][j] = 0.f;

    // prologue: stage k-tiles 0 and 1
    #pragma unroll
    for (int p = 0; p < 2; p++) {
        const int kt = p * 32;
        const uint32_t xd = xb[p] + (uint32_t)(xr*GST2)*4;
        const unsigned short* xs = X + (size_t)(m0 + xr)*Hh + kt;
        CPASYNC16(xd + xc*16,      xs + xc*8);
        CPASYNC16(xd + (xc+1)*16,  xs + (xc+1)*8);
        CPASYNC16(wb[p] + (uint32_t)(wr*GST2)*4 + wc*16, W + (size_t)(n0b + wr)*Hh + kt + wc*8);
        CPCOMMIT();
    }

    for (int i = 0; i < 16; i++) {
        if (i < 14) {
            const int kt = (i + 2) * 32, bf = (i + 2) % 3;
            const uint32_t xd = xb[bf] + (uint32_t)(xr*GST2)*4;
            const unsigned short* xs = X + (size_t)(m0 + xr)*Hh + kt;
            CPASYNC16(xd + xc*16,     xs + xc*8);
            CPASYNC16(xd + (xc+1)*16, xs + (xc+1)*8);
            CPASYNC16(wb[bf] + (uint32_t)(wr*GST2)*4 + wc*16, W + (size_t)(n0b + wr)*Hh + kt + wc*8);
            CPCOMMIT();
            asm volatile("cp.async.wait_group 2;" ::: "memory");
        } else if (i == 14) {
            asm volatile("cp.async.wait_group 1;" ::: "memory");
        } else {
            asm volatile("cp.async.wait_group 0;" ::: "memory");
        }
        __syncthreads();

        const uint32_t xa = xb[i % 3], wa = wb[i % 3];
        uint32_t a[2][4];
        LDSM4(a[0], xa + aoff);
        LDSM4(a[1], xa + aoff + 32);
        #pragma unroll
        for (int n0 = 0; n0 < 8; n0++) {
            uint32_t bbr[4];
            LDSM4(bbr, wa + (uint32_t)n0*(8*GST2*4) + boff);
            MMA16(acc[n0], a[0][0], a[0][1], a[0][2], a[0][3], bbr[0], bbr[1]);
            MMA16(acc[n0], a[1][0], a[1][1], a[1][2], a[1][3], bbr[2], bbr[3]);
        }
        __syncthreads();
    }

    const int mr0 = m0 + warp*16 + g;
    #pragma unroll
    for (int n0 = 0; n0 < 8; n0++) {
        const int n = n0b + n0*8 + 2*q;
        const float bv0 = bias[n], bv1 = bias[n+1];
        float v[2][2] = {{acc[n0][0]+bv0, acc[n0][1]+bv1}, {acc[n0][2]+bv0, acc[n0][3]+bv1}};
        if (mode == 0) {
            float* out = (float*)outv;
            *(float2*)(out + (size_t)mr0*Hh + n)     = make_float2(v[0][0], v[0][1]);
            *(float2*)(out + (size_t)(mr0+8)*Hh + n) = make_float2(v[1][0], v[1][1]);
        } else {
            unsigned short* outH = (unsigned short*)outv;
            if (mode == 1) { v[0][0]*=QSCALE; v[0][1]*=QSCALE; v[1][0]*=QSCALE; v[1][1]*=QSCALE; }
            const int nh = n >> 6, hd = n & 63;
            #pragma unroll
            for (int r = 0; r < 2; r++) {
                const int m = mr0 + r*8, b = m >> 11, s = m & (Ss-1);
                if (mode == 3) {
                    __half h0 = __float2half_rn(v[r][0]), h1 = __float2half_rn(v[r][1]);
                    outH[(((size_t)b*NHh + nh)*HDd + hd)*Ss + s]     = *(unsigned short*)&h0;
                    outH[(((size_t)b*NHh + nh)*HDd + hd + 1)*Ss + s] = *(unsigned short*)&h1;
                } else {
                    *(uint32_t*)(outH + (((size_t)b*NHh + nh)*Ss + s)*HDd + hd) = pack2(v[r][0], v[r][1]);
                }
            }
        }
    }
}

// fused Q/K/V projections: gridDim.z = 3 selects problem
__global__ __launch_bounds__(256) void gemm_qkv(
    const unsigned short* __restrict__ Xq, const unsigned short* __restrict__ Xk,
    const unsigned short* __restrict__ Xv, const unsigned short* __restrict__ Wh,
    const float* __restrict__ bq, const float* __restrict__ bk, const float* __restrict__ bv,
    unsigned short* __restrict__ Qp, unsigned short* __restrict__ Kp, unsigned short* __restrict__ Vp)
{
    const int z = blockIdx.z;
    const unsigned short* X = (z == 0) ? Xq : (z == 1) ? Xk : Xv;
    const float* bias = (z == 0) ? bq : (z == 1) ? bk : bv;
    unsigned short* out = (z == 0) ? Qp : (z == 1) ? Kp : Vp;
    gemm_core(X, Wh + (size_t)z*Hh*Hh, bias, out, z + 1);
}

__global__ __launch_bounds__(256) void gemm_out(
    const unsigned short* __restrict__ X, const unsigned short* __restrict__ W,
    const float* __restrict__ bias, float* __restrict__ out)
{
    gemm_core(X, W, bias, out, 0);
}

// ---------------------------------------------------------------------------
// fp16 flash attention (unchanged from R8/R10)
// ---------------------------------------------------------------------------
#define KST 36
#define TILE_W (64*KST)
#define NT (Ss/64)

__global__ __launch_bounds__(256) void attn_h2(
    const uint32_t* __restrict__ pm, const unsigned short* __restrict__ Q,
    const unsigned short* __restrict__ K, const unsigned short* __restrict__ V,
    unsigned short* __restrict__ A)
{
    __shared__ uint32_t sKV[4 * TILE_W];

    const int tid = threadIdx.x, warp = tid >> 5, lane = tid & 31;
    const int g = lane >> 2, q = lane & 3;
    const int bh = blockIdx.y, b = bh >> 3, nh = bh & 7;
    const int q0 = blockIdx.x << 7;
    const int r0 = q0 + warp*16 + g;

    const unsigned short* Qh = Q + (size_t)bh*Ss*HDd;
    const unsigned short* Kh = K + (size_t)bh*Ss*HDd;
    const unsigned short* Vh = V + (size_t)bh*HDd*Ss;

    const uint32_t base = smem_u32(&sKV[0]);
    const uint32_t Kb[2] = { base, base + TILE_W*4 };
    const uint32_t Vb[2] = { base + 2*TILE_W*4, base + 3*TILE_W*4 };
    const uint32_t lmoff = (uint32_t)(((lane & 7)*KST + ((lane >> 3) << 2)) * 4);

    uint32_t qa[4][4];
    #pragma unroll
    for (int kk = 0; kk < 4; kk++) {
        qa[kk][0] = *(const uint32_t*)(Qh + (size_t)r0*HDd     + kk*16 + 2*q);
        qa[kk][1] = *(const uint32_t*)(Qh + (size_t)(r0+8)*HDd + kk*16 + 2*q);
        qa[kk][2] = *(const uint32_t*)(Qh + (size_t)r0*HDd     + kk*16 + 2*q + 8);
        qa[kk][3] = *(const uint32_t*)(Qh + (size_t)(r0+8)*HDd + kk*16 + 2*q + 8);
    }

    float o[8][4];
    #pragma unroll
    for (int i = 0; i < 8; i++)
        #pragma unroll
        for (int j = 0; j < 4; j++) o[i][j] = 0.f;
    float l0 = 0.f, l1 = 0.f;

    const uint32_t* pmr0 = pm + ((size_t)b*Ss + r0)*(Ss/32);
    const uint32_t* pmr1 = pmr0 + 8*(Ss/32);
    const int sh = 2*q;

    #pragma unroll
    for (int i = 0; i < 2; i++) {
        const int fid = tid + i*256, r = fid >> 3, ch = fid & 7;
        CPASYNC16(Kb[0] + (uint32_t)(r*KST + ch*4)*4, Kh + (size_t)r*HDd + ch*8);
        CPASYNC16(Vb[0] + (uint32_t)(r*KST + ch*4)*4, Vh + (size_t)r*Ss + ch*8);
    }
    CPCOMMIT();

    for (int t = 0; t < NT; t++) {
        if (t + 1 < NT) {
            const int k0n = (t + 1) << 6, bf = (t + 1) & 1;
            #pragma unroll
            for (int i = 0; i < 2; i++) {
                const int fid = tid + i*256, r = fid >> 3, ch = fid & 7;
                CPASYNC16(Kb[bf] + (uint32_t)(r*KST + ch*4)*4, Kh + (size_t)(k0n + r)*HDd + ch*8);
                CPASYNC16(Vb[bf] + (uint32_t)(r*KST + ch*4)*4, Vh + (size_t)r*Ss + k0n + ch*8);
            }
            CPCOMMIT();
            asm volatile("cp.async.wait_group 1;" ::: "memory");
        } else {
            asm volatile("cp.async.wait_group 0;" ::: "memory");
        }
        __syncthreads();

        const uint32_t Ka = Kb[t & 1], Va = Vb[t & 1];

        float sc[8][4];
        #pragma unroll
        for (int i = 0; i < 8; i++)
            #pragma unroll
            for (int j = 0; j < 4; j++) sc[i][j] = 0.f;
        #pragma unroll
        for (int n0 = 0; n0 < 8; n0++) {
            uint32_t bbr[8];
            LDSM4(bbr,     Ka + (uint32_t)n0*(8*KST*4) + lmoff);
            LDSM4(bbr + 4, Ka + (uint32_t)n0*(8*KST*4) + lmoff + 64);
            MMA16(sc[n0], qa[0][0], qa[0][1], qa[0][2], qa[0][3], bbr[0], bbr[1]);
            MMA16(sc[n0], qa[1][0], qa[1][1], qa[1][2], qa[1][3], bbr[2], bbr[3]);
            MMA16(sc[n0], qa[2][0], qa[2][1], qa[2][2], qa[2][3], bbr[4], bbr[5]);
            MMA16(sc[n0], qa[3][0], qa[3][1], qa[3][2], qa[3][3], bbr[6], bbr[7]);
        }

        const uint32_t mw0[2] = { pmr0[2*t], pmr0[2*t + 1] };
        const uint32_t mw1[2] = { pmr1[2*t], pmr1[2*t + 1] };
        #pragma unroll
        for (int n0 = 0; n0 < 8; n0++) {
            const int w = n0 >> 2, s2 = ((n0 & 3) << 3) + sh;
            const uint32_t b0m = (mw0[w] >> s2) & 3u;
            const uint32_t b1m = (mw1[w] >> s2) & 3u;
            sc[n0][0] = (b0m & 1u) ? ex2f(fminf(sc[n0][0], 15.f)) : 0.f;
            sc[n0][1] = (b0m & 2u) ? ex2f(fminf(sc[n0][1], 15.f)) : 0.f;
            sc[n0][2] = (b1m & 1u) ? ex2f(fminf(sc[n0][2], 15.f)) : 0.f;
            sc[n0][3] = (b1m & 2u) ? ex2f(fminf(sc[n0][3], 15.f)) : 0.f;
            l0 += sc[n0][0] + sc[n0][1];
            l1 += sc[n0][2] + sc[n0][3];
        }

        uint32_t pp[4][4];
        #pragma unroll
        for (int kk = 0; kk < 4; kk++) {
            pp[kk][0] = pack2(sc[2*kk][0],   sc[2*kk][1]);
            pp[kk][1] = pack2(sc[2*kk][2],   sc[2*kk][3]);
            pp[kk][2] = pack2(sc[2*kk+1][0], sc[2*kk+1][1]);
            pp[kk][3] = pack2(sc[2*kk+1][2], sc[2*kk+1][3]);
        }

        #pragma unroll
        for (int n0 = 0; n0 < 8; n0++) {
            uint32_t bbr[8];
            LDSM4(bbr,     Va + (uint32_t)n0*(8*KST*4) + lmoff);
            LDSM4(bbr + 4, Va + (uint32_t)n0*(8*KST*4) + lmoff + 64);
            MMA16(o[n0], pp[0][0], pp[0][1], pp[0][2], pp[0][3], bbr[0], bbr[1]);
            MMA16(o[n0], pp[1][0], pp[1][1], pp[1][2], pp[1][3], bbr[2], bbr[3]);
            MMA16(o[n0], pp[2][0], pp[2][1], pp[2][2], pp[2][3], bbr[4], bbr[5]);
            MMA16(o[n0], pp[3][0], pp[3][1], pp[3][2], pp[3][3], bbr[6], bbr[7]);
        }
        __syncthreads();
    }

    l0 += __shfl_xor_sync(0xffffffffu, l0, 1);
    l0 += __shfl_xor_sync(0xffffffffu, l0, 2);
    l1 += __shfl_xor_sync(0xffffffffu, l1, 1);
    l1 += __shfl_xor_sync(0xffffffffu, l1, 2);
    const float inv0 = 1.f / l0, inv1 = 1.f / l1;

    #pragma unroll
    for (int n0 = 0; n0 < 8; n0++) {
        const int hd = n0*8 + 2*q;
        *(uint32_t*)(A + ((size_t)b*Ss + r0)*Hh + nh*HDd + hd) =
            pack2(o[n0][0]*inv0, o[n0][1]*inv0);
        *(uint32_t*)(A + ((size_t)b*Ss + r0 + 8)*Hh + nh*HDd + hd) =
            pack2(o[n0][2]*inv1, o[n0][3]*inv1);
    }
}

// ---------------------------------------------------------------------------
extern "C" void kernel_launch(void* const* d_in, const int* in_sizes, int n_in,
                              void* d_out, int out_size)
{
    const float* q  = (const float*)d_in[0];
    const float* k  = (const float*)d_in[1];
    const float* v  = (const float*)d_in[2];
    const int*   mk = (const int*)  d_in[3];
    const float* Wq = (const float*)d_in[4];
    const float* bq = (const float*)d_in[5];
    const float* Wk = (const float*)d_in[6];
    const float* bk = (const float*)d_in[7];
    const float* Wv = (const float*)d_in[8];
    const float* bv = (const float*)d_in[9];
    const float* Wo = (const float*)d_in[10];
    const float* bo = (const float*)d_in[11];

    unsigned short *Qp, *Kp, *Vp, *Ap, *Xq, *Xk, *Xv, *Wh;
    uint32_t* Mp;
    cudaGetSymbolAddress((void**)&Qp, g_Q);
    cudaGetSymbolAddress((void**)&Kp, g_K);
    cudaGetSymbolAddress((void**)&Vp, g_V);
    cudaGetSymbolAddress((void**)&Ap, g_A);
    cudaGetSymbolAddress((void**)&Xq, g_Xq);
    cudaGetSymbolAddress((void**)&Xk, g_Xk);
    cudaGetSymbolAddress((void**)&Xv, g_Xv);
    cudaGetSymbolAddress((void**)&Wh, g_Wh);
    cudaGetSymbolAddress((void**)&Mp, g_M);

    conv_all<<<CONV_BLOCKS, 256>>>(q, k, v, Wq, Wk, Wv, Wo, mk,
                                   Xq, Xk, Xv, Wh, Mp);
    gemm_qkv<<<dim3(Hh/64, Mm/128, 3), 256>>>(Xq, Xk, Xv, Wh, bq, bk, bv, Qp, Kp, Vp);
    attn_h2<<<dim3(Ss/128, Bb*NHh), 256>>>(Mp, Qp, Kp, Vp, Ap);
    gemm_out<<<dim3(Hh/64, Mm/128), 256>>>(Ap, Wh + 3*(size_t)Hh*Hh, bo, (float*)d_out);
}

// round 13
// speedup vs baseline: 1.0292x; 1.0292x over previous
#include <cuda_runtime.h>
#include <cuda_fp16.h>
#include <cstdint>
#include <cstddef>

#define Bb   4
#define Ss   2048
#define Hh   512
#define NHh  8
#define HDd  64
#define Mm   (Bb*Ss)

// half scratch buffers
__device__ unsigned short g_Q[(size_t)Bb*NHh*Ss*HDd];  // [b,nh,s,hd], *0.125*log2e
__device__ unsigned short g_K[(size_t)Bb*NHh*Ss*HDd];  // [b,nh,s,hd]
__device__ unsigned short g_V[(size_t)Bb*NHh*Ss*HDd];  // [b,nh,hd,s] TRANSPOSED
__device__ unsigned short g_A[(size_t)Mm*Hh];          // [b,s,h]
// pre-converted half inputs
__device__ unsigned short g_Xq[(size_t)Mm*Hh];
__device__ unsigned short g_Xk[(size_t)Mm*Hh];
__device__ unsigned short g_Xv[(size_t)Mm*Hh];
__device__ unsigned short g_Wh[(size_t)4*Hh*Hh];
// packed mask bits: [b][s][64 words]
__device__ uint32_t g_M[(size_t)Bb*Ss*(Ss/32)];

#define QSCALE 0.1803368801111204f   // 0.125 * log2(e)

__device__ __forceinline__ uint32_t smem_u32(const void* p) {
    uint32_t a;
    asm("{ .reg .u64 t; cvta.to.shared.u64 t, %1; cvt.u32.u64 %0, t; }" : "=r"(a) : "l"(p));
    return a;
}
__device__ __forceinline__ float ex2f(float x) {
    float r; asm("ex2.approx.f32 %0, %1;" : "=f"(r) : "f"(x)); return r;
}
__device__ __forceinline__ uint32_t pack2(float a, float b) {
    __half2 h = __floats2half2_rn(a, b);
    return *(uint32_t*)&h;
}
#define CPASYNC16(dst, src) \
    asm volatile("cp.async.cg.shared.global [%0], [%1], 16;" :: "r"(dst), "l"(src))
#define CPCOMMIT() asm volatile("cp.async.commit_group;" ::: "memory")

#define MMA16(d, a0, a1, a2, a3, b0, b1) \
    asm volatile("mma.sync.aligned.m16n8k16.row.col.f32.f16.f16.f32 " \
        "{%0,%1,%2,%3}, {%4,%5,%6,%7}, {%8,%9}, {%0,%1,%2,%3};" \
        : "+f"((d)[0]), "+f"((d)[1]), "+f"((d)[2]), "+f"((d)[3]) \
        : "r"(a0), "r"(a1), "r"(a2), "r"(a3), "r"(b0), "r"(b1))

#define LDSM4(r, addr) \
    asm volatile("ldmatrix.sync.aligned.m8n8.x4.shared.b16 {%0,%1,%2,%3}, [%4];" \
        : "=r"((r)[0]), "=r"((r)[1]), "=r"((r)[2]), "=r"((r)[3]) : "r"(addr))

// ---------------------------------------------------------------------------
// fused pre-pass: convert q/k/v and 4 weights to half, pack mask bits.
// ---------------------------------------------------------------------------
#define NX4 ((int)((size_t)Mm*Hh/4))        // 1048576
#define NW4 (Hh*Hh/4)                       // 65536
#define NMW ((int)((size_t)Bb*Ss*(Ss/32)))  // 524288
#define CONV_BLOCKS ((3*NX4 + 4*NW4 + NMW)/256)

__global__ __launch_bounds__(256) void conv_all(
    const float* __restrict__ q, const float* __restrict__ k, const float* __restrict__ v,
    const float* __restrict__ Wq, const float* __restrict__ Wk,
    const float* __restrict__ Wv, const float* __restrict__ Wo,
    const int* __restrict__ msk,
    unsigned short* __restrict__ Xq, unsigned short* __restrict__ Xk,
    unsigned short* __restrict__ Xv, unsigned short* __restrict__ Wh,
    uint32_t* __restrict__ Mo)
{
    const int i = blockIdx.x*256 + threadIdx.x;
    if (i < 3*NX4) {
        const int z = i / NX4, idx = i - z*NX4;
        const float* src = (z == 0) ? q : (z == 1) ? k : v;
        unsigned short* dst = (z == 0) ? Xq : (z == 1) ? Xk : Xv;
        float4 f = ((const float4*)src)[idx];
        uint2 o; o.x = pack2(f.x, f.y); o.y = pack2(f.z, f.w);
        ((uint2*)dst)[idx] = o;
    } else if (i < 3*NX4 + 4*NW4) {
        const int j = i - 3*NX4, z = j / NW4, idx = j - z*NW4;
        const float* src = (z == 0) ? Wq : (z == 1) ? Wk : (z == 2) ? Wv : Wo;
        unsigned short* dst = Wh + (size_t)z*Hh*Hh;
        float4 f = ((const float4*)src)[idx];
        uint2 o; o.x = pack2(f.x, f.y); o.y = pack2(f.z, f.w);
        ((uint2*)dst)[idx] = o;
    } else {
        const int w = i - (3*NX4 + 4*NW4);
        const int4* src = (const int4*)(msk + (size_t)w*32);
        uint32_t bits = 0;
        #pragma unroll
        for (int t = 0; t < 8; t++) {
            int4 m = src[t];
            bits |= ((uint32_t)(m.x != 0) << (4*t))   | ((uint32_t)(m.y != 0) << (4*t+1))
                  | ((uint32_t)(m.z != 0) << (4*t+2)) | ((uint32_t)(m.w != 0) << (4*t+3));
        }
        Mo[w] = bits;
    }
}

// ---------------------------------------------------------------------------
// fp16 GEMM core, 3-stage cp.async pipeline, ONE __syncthreads per k-iter.
// Order: wait -> SYNC -> prefetch(i+2) -> compute(i).
// Prefetch at i targets buf (i+2)%3 == buffer read at i-1; the sync proves
// all warps finished iter i-1, so the overwrite is safe with a single barrier.
// ---------------------------------------------------------------------------
#define GST2 20    // words per row (16 data + 4 pad)

__device__ __forceinline__ void gemm_core(
    const unsigned short* __restrict__ X, const unsigned short* __restrict__ W,
    const float* __restrict__ bias, void* __restrict__ outv, int mode)
{
    __shared__ uint32_t Xs[3][128*GST2];
    __shared__ uint32_t Ws[3][64*GST2];
    const int tid = threadIdx.x, warp = tid >> 5, lane = tid & 31;
    const int g = lane >> 2, q = lane & 3;
    const int m0 = blockIdx.y << 7, n0b = blockIdx.x << 6;

    const int xr = tid >> 1, xc = (tid & 1) * 2;
    const int wr = tid >> 2, wc = tid & 3;

    const uint32_t xb[3] = { smem_u32(&Xs[0][0]), smem_u32(&Xs[1][0]), smem_u32(&Xs[2][0]) };
    const uint32_t wb[3] = { smem_u32(&Ws[0][0]), smem_u32(&Ws[1][0]), smem_u32(&Ws[2][0]) };
    const uint32_t aoff = (uint32_t)(((warp*16 + ((lane >> 3) & 1)*8 + (lane & 7))*GST2
                          + ((lane >> 4) << 2)) * 4);
    const uint32_t boff = (uint32_t)(((lane & 7)*GST2 + ((lane >> 3) << 2)) * 4);

    float acc[8][4];
    #pragma unroll
    for (int i = 0; i < 8; i++)
        #pragma unroll
        for (int j = 0; j < 4; j++) acc[i][j] = 0.f;

    // prologue: stage k-tiles 0 and 1 into bufs 0,1
    #pragma unroll
    for (int p = 0; p < 2; p++) {
        const int kt = p * 32;
        const uint32_t xd = xb[p] + (uint32_t)(xr*GST2)*4;
        const unsigned short* xs = X + (size_t)(m0 + xr)*Hh + kt;
        CPASYNC16(xd + xc*16,      xs + xc*8);
        CPASYNC16(xd + (xc+1)*16,  xs + (xc+1)*8);
        CPASYNC16(wb[p] + (uint32_t)(wr*GST2)*4 + wc*16, W + (size_t)(n0b + wr)*Hh + kt + wc*8);
        CPCOMMIT();
    }

    for (int i = 0; i < 16; i++) {
        if (i < 15) asm volatile("cp.async.wait_group 1;" ::: "memory");
        else        asm volatile("cp.async.wait_group 0;" ::: "memory");
        __syncthreads();

        if (i < 14) {
            const int kt = (i + 2) * 32, bf = (i + 2) % 3;
            const uint32_t xd = xb[bf] + (uint32_t)(xr*GST2)*4;
            const unsigned short* xs = X + (size_t)(m0 + xr)*Hh + kt;
            CPASYNC16(xd + xc*16,     xs + xc*8);
            CPASYNC16(xd + (xc+1)*16, xs + (xc+1)*8);
            CPASYNC16(wb[bf] + (uint32_t)(wr*GST2)*4 + wc*16, W + (size_t)(n0b + wr)*Hh + kt + wc*8);
            CPCOMMIT();
        }

        const uint32_t xa = xb[i % 3], wa = wb[i % 3];
        uint32_t a[2][4];
        LDSM4(a[0], xa + aoff);
        LDSM4(a[1], xa + aoff + 32);
        #pragma unroll
        for (int n0 = 0; n0 < 8; n0++) {
            uint32_t bbr[4];
            LDSM4(bbr, wa + (uint32_t)n0*(8*GST2*4) + boff);
            MMA16(acc[n0], a[0][0], a[0][1], a[0][2], a[0][3], bbr[0], bbr[1]);
            MMA16(acc[n0], a[1][0], a[1][1], a[1][2], a[1][3], bbr[2], bbr[3]);
        }
    }

    const int mr0 = m0 + warp*16 + g;
    #pragma unroll
    for (int n0 = 0; n0 < 8; n0++) {
        const int n = n0b + n0*8 + 2*q;
        const float bv0 = bias[n], bv1 = bias[n+1];
        float v[2][2] = {{acc[n0][0]+bv0, acc[n0][1]+bv1}, {acc[n0][2]+bv0, acc[n0][3]+bv1}};
        if (mode == 0) {
            float* out = (float*)outv;
            *(float2*)(out + (size_t)mr0*Hh + n)     = make_float2(v[0][0], v[0][1]);
            *(float2*)(out + (size_t)(mr0+8)*Hh + n) = make_float2(v[1][0], v[1][1]);
        } else {
            unsigned short* outH = (unsigned short*)outv;
            if (mode == 1) { v[0][0]*=QSCALE; v[0][1]*=QSCALE; v[1][0]*=QSCALE; v[1][1]*=QSCALE; }
            const int nh = n >> 6, hd = n & 63;
            #pragma unroll
            for (int r = 0; r < 2; r++) {
                const int m = mr0 + r*8, b = m >> 11, s = m & (Ss-1);
                if (mode == 3) {
                    __half h0 = __float2half_rn(v[r][0]), h1 = __float2half_rn(v[r][1]);
                    outH[(((size_t)b*NHh + nh)*HDd + hd)*Ss + s]     = *(unsigned short*)&h0;
                    outH[(((size_t)b*NHh + nh)*HDd + hd + 1)*Ss + s] = *(unsigned short*)&h1;
                } else {
                    *(uint32_t*)(outH + (((size_t)b*NHh + nh)*Ss + s)*HDd + hd) = pack2(v[r][0], v[r][1]);
                }
            }
        }
    }
}

// fused Q/K/V projections: gridDim.z = 3 selects problem
__global__ __launch_bounds__(256) void gemm_qkv(
    const unsigned short* __restrict__ Xq, const unsigned short* __restrict__ Xk,
    const unsigned short* __restrict__ Xv, const unsigned short* __restrict__ Wh,
    const float* __restrict__ bq, const float* __restrict__ bk, const float* __restrict__ bv,
    unsigned short* __restrict__ Qp, unsigned short* __restrict__ Kp, unsigned short* __restrict__ Vp)
{
    const int z = blockIdx.z;
    const unsigned short* X = (z == 0) ? Xq : (z == 1) ? Xk : Xv;
    const float* bias = (z == 0) ? bq : (z == 1) ? bk : bv;
    unsigned short* out = (z == 0) ? Qp : (z == 1) ? Kp : Vp;
    gemm_core(X, Wh + (size_t)z*Hh*Hh, bias, out, z + 1);
}

__global__ __launch_bounds__(256) void gemm_out(
    const unsigned short* __restrict__ X, const unsigned short* __restrict__ W,
    const float* __restrict__ bias, float* __restrict__ out)
{
    gemm_core(X, W, bias, out, 0);
}

// ---------------------------------------------------------------------------
// fp16 flash attention, ONE __syncthreads per KV tile.
// Order: wait -> SYNC -> prefetch(t+1) -> compute(t).
// Prefetch at t targets buf (t+1)&1 == buffer read at t-1; the sync proves
// all warps finished tile t-1, so a single barrier is sufficient.
// ---------------------------------------------------------------------------
#define KST 36
#define TILE_W (64*KST)
#define NT (Ss/64)

__global__ __launch_bounds__(256) void attn_h2(
    const uint32_t* __restrict__ pm, const unsigned short* __restrict__ Q,
    const unsigned short* __restrict__ K, const unsigned short* __restrict__ V,
    unsigned short* __restrict__ A)
{
    __shared__ uint32_t sKV[4 * TILE_W];

    const int tid = threadIdx.x, warp = tid >> 5, lane = tid & 31;
    const int g = lane >> 2, q = lane & 3;
    const int bh = blockIdx.y, b = bh >> 3, nh = bh & 7;
    const int q0 = blockIdx.x << 7;
    const int r0 = q0 + warp*16 + g;

    const unsigned short* Qh = Q + (size_t)bh*Ss*HDd;
    const unsigned short* Kh = K + (size_t)bh*Ss*HDd;
    const unsigned short* Vh = V + (size_t)bh*HDd*Ss;

    const uint32_t base = smem_u32(&sKV[0]);
    const uint32_t Kb[2] = { base, base + TILE_W*4 };
    const uint32_t Vb[2] = { base + 2*TILE_W*4, base + 3*TILE_W*4 };
    const uint32_t lmoff = (uint32_t)(((lane & 7)*KST + ((lane >> 3) << 2)) * 4);

    uint32_t qa[4][4];
    #pragma unroll
    for (int kk = 0; kk < 4; kk++) {
        qa[kk][0] = *(const uint32_t*)(Qh + (size_t)r0*HDd     + kk*16 + 2*q);
        qa[kk][1] = *(const uint32_t*)(Qh + (size_t)(r0+8)*HDd + kk*16 + 2*q);
        qa[kk][2] = *(const uint32_t*)(Qh + (size_t)r0*HDd     + kk*16 + 2*q + 8);
        qa[kk][3] = *(const uint32_t*)(Qh + (size_t)(r0+8)*HDd + kk*16 + 2*q + 8);
    }

    float o[8][4];
    #pragma unroll
    for (int i = 0; i < 8; i++)
        #pragma unroll
        for (int j = 0; j < 4; j++) o[i][j] = 0.f;
    float l0 = 0.f, l1 = 0.f;

    const uint32_t* pmr0 = pm + ((size_t)b*Ss + r0)*(Ss/32);
    const uint32_t* pmr1 = pmr0 + 8*(Ss/32);
    const int sh = 2*q;

    // prologue: tile 0 into buffer 0
    #pragma unroll
    for (int i = 0; i < 2; i++) {
        const int fid = tid + i*256, r = fid >> 3, ch = fid & 7;
        CPASYNC16(Kb[0] + (uint32_t)(r*KST + ch*4)*4, Kh + (size_t)r*HDd + ch*8);
        CPASYNC16(Vb[0] + (uint32_t)(r*KST + ch*4)*4, Vh + (size_t)r*Ss + ch*8);
    }
    CPCOMMIT();

    for (int t = 0; t < NT; t++) {
        asm volatile("cp.async.wait_group 0;" ::: "memory");
        __syncthreads();

        if (t + 1 < NT) {
            const int k0n = (t + 1) << 6, bf = (t + 1) & 1;
            #pragma unroll
            for (int i = 0; i < 2; i++) {
                const int fid = tid + i*256, r = fid >> 3, ch = fid & 7;
                CPASYNC16(Kb[bf] + (uint32_t)(r*KST + ch*4)*4, Kh + (size_t)(k0n + r)*HDd + ch*8);
                CPASYNC16(Vb[bf] + (uint32_t)(r*KST + ch*4)*4, Vh + (size_t)r*Ss + k0n + ch*8);
            }
            CPCOMMIT();
        }

        const uint32_t Ka = Kb[t & 1], Va = Vb[t & 1];

        float sc[8][4];
        #pragma unroll
        for (int i = 0; i < 8; i++)
            #pragma unroll
            for (int j = 0; j < 4; j++) sc[i][j] = 0.f;
        #pragma unroll
        for (int n0 = 0; n0 < 8; n0++) {
            uint32_t bbr[8];
            LDSM4(bbr,     Ka + (uint32_t)n0*(8*KST*4) + lmoff);
            LDSM4(bbr + 4, Ka + (uint32_t)n0*(8*KST*4) + lmoff + 64);
            MMA16(sc[n0], qa[0][0], qa[0][1], qa[0][2], qa[0][3], bbr[0], bbr[1]);
            MMA16(sc[n0], qa[1][0], qa[1][1], qa[1][2], qa[1][3], bbr[2], bbr[3]);
            MMA16(sc[n0], qa[2][0], qa[2][1], qa[2][2], qa[2][3], bbr[4], bbr[5]);
            MMA16(sc[n0], qa[3][0], qa[3][1], qa[3][2], qa[3][3], bbr[6], bbr[7]);
        }

        const uint32_t mw0[2] = { pmr0[2*t], pmr0[2*t + 1] };
        const uint32_t mw1[2] = { pmr1[2*t], pmr1[2*t + 1] };
        #pragma unroll
        for (int n0 = 0; n0 < 8; n0++) {
            const int w = n0 >> 2, s2 = ((n0 & 3) << 3) + sh;
            const uint32_t b0m = (mw0[w] >> s2) & 3u;
            const uint32_t b1m = (mw1[w] >> s2) & 3u;
            sc[n0][0] = (b0m & 1u) ? ex2f(fminf(sc[n0][0], 15.f)) : 0.f;
            sc[n0][1] = (b0m & 2u) ? ex2f(fminf(sc[n0][1], 15.f)) : 0.f;
            sc[n0][2] = (b1m & 1u) ? ex2f(fminf(sc[n0][2], 15.f)) : 0.f;
            sc[n0][3] = (b1m & 2u) ? ex2f(fminf(sc[n0][3], 15.f)) : 0.f;
            l0 += sc[n0][0] + sc[n0][1];
            l1 += sc[n0][2] + sc[n0][3];
        }

        uint32_t pp[4][4];
        #pragma unroll
        for (int kk = 0; kk < 4; kk++) {
            pp[kk][0] = pack2(sc[2*kk][0],   sc[2*kk][1]);
            pp[kk][1] = pack2(sc[2*kk][2],   sc[2*kk][3]);
            pp[kk][2] = pack2(sc[2*kk+1][0], sc[2*kk+1][1]);
            pp[kk][3] = pack2(sc[2*kk+1][2], sc[2*kk+1][3]);
        }

        #pragma unroll
        for (int n0 = 0; n0 < 8; n0++) {
            uint32_t bbr[8];
            LDSM4(bbr,     Va + (uint32_t)n0*(8*KST*4) + lmoff);
            LDSM4(bbr + 4, Va + (uint32_t)n0*(8*KST*4) + lmoff + 64);
            MMA16(o[n0], pp[0][0], pp[0][1], pp[0][2], pp[0][3], bbr[0], bbr[1]);
            MMA16(o[n0], pp[1][0], pp[1][1], pp[1][2], pp[1][3], bbr[2], bbr[3]);
            MMA16(o[n0], pp[2][0], pp[2][1], pp[2][2], pp[2][3], bbr[4], bbr[5]);
            MMA16(o[n0], pp[3][0], pp[3][1], pp[3][2], pp[3][3], bbr[6], bbr[7]);
        }
    }

    l0 += __shfl_xor_sync(0xffffffffu, l0, 1);
    l0 += __shfl_xor_sync(0xffffffffu, l0, 2);
    l1 += __shfl_xor_sync(0xffffffffu, l1, 1);
    l1 += __shfl_xor_sync(0xffffffffu, l1, 2);
    const float inv0 = 1.f / l0, inv1 = 1.f / l1;

    #pragma unroll
    for (int n0 = 0; n0 < 8; n0++) {
        const int hd = n0*8 + 2*q;
        *(uint32_t*)(A + ((size_t)b*Ss + r0)*Hh + nh*HDd + hd) =
            pack2(o[n0][0]*inv0, o[n0][1]*inv0);
        *(uint32_t*)(A + ((size_t)b*Ss + r0 + 8)*Hh + nh*HDd + hd) =
            pack2(o[n0][2]*inv1, o[n0][3]*inv1);
    }
}

// ---------------------------------------------------------------------------
extern "C" void kernel_launch(void* const* d_in, const int* in_sizes, int n_in,
                              void* d_out, int out_size)
{
    const float* q  = (const float*)d_in[0];
    const float* k  = (const float*)d_in[1];
    const float* v  = (const float*)d_in[2];
    const int*   mk = (const int*)  d_in[3];
    const float* Wq = (const float*)d_in[4];
    const float* bq = (const float*)d_in[5];
    const float* Wk = (const float*)d_in[6];
    const float* bk = (const float*)d_in[7];
    const float* Wv = (const float*)d_in[8];
    const float* bv = (const float*)d_in[9];
    const float* Wo = (const float*)d_in[10];
    const float* bo = (const float*)d_in[11];

    unsigned short *Qp, *Kp, *Vp, *Ap, *Xq, *Xk, *Xv, *Wh;
    uint32_t* Mp;
    cudaGetSymbolAddress((void**)&Qp, g_Q);
    cudaGetSymbolAddress((void**)&Kp, g_K);
    cudaGetSymbolAddress((void**)&Vp, g_V);
    cudaGetSymbolAddress((void**)&Ap, g_A);
    cudaGetSymbolAddress((void**)&Xq, g_Xq);
    cudaGetSymbolAddress((void**)&Xk, g_Xk);
    cudaGetSymbolAddress((void**)&Xv, g_Xv);
    cudaGetSymbolAddress((void**)&Wh, g_Wh);
    cudaGetSymbolAddress((void**)&Mp, g_M);

    conv_all<<<CONV_BLOCKS, 256>>>(q, k, v, Wq, Wk, Wv, Wo, mk,
                                   Xq, Xk, Xv, Wh, Mp);
    gemm_qkv<<<dim3(Hh/64, Mm/128, 3), 256>>>(Xq, Xk, Xv, Wh, bq, bk, bv, Qp, Kp, Vp);
    attn_h2<<<dim3(Ss/128, Bb*NHh), 256>>>(Mp, Qp, Kp, Vp, Ap);
    gemm_out<<<dim3(Hh/64, Mm/128), 256>>>(Ap, Wh + 3*(size_t)Hh*Hh, bo, (float*)d_out);
}